// round 1
// baseline (speedup 1.0000x reference)
#include <cuda_runtime.h>
#include <math.h>

#define CC   256
#define NN   4096
#define DD   32
#define BATCH 8
#define BM   64
#define BN   64

// Scratch for projections (q/k: [b][n][32], v: [b][n][256])
__device__ float g_q[BATCH * NN * DD];
__device__ float g_k[BATCH * NN * DD];
__device__ float g_v[(size_t)BATCH * NN * CC];

// ---------------------------------------------------------------------------
// Kernel 1: fused QKV projection.
// Block handles (b, 32 pixels). Loops over channel chunks of 32:
//   stages x[32c][32n] and W[320d][32c] in smem, each thread owns 5 d x 8 n.
// ---------------------------------------------------------------------------
__global__ __launch_bounds__(256) void proj_kernel(
    const float* __restrict__ x,
    const float* __restrict__ Wq, const float* __restrict__ bq,
    const float* __restrict__ Wk, const float* __restrict__ bk,
    const float* __restrict__ Wv, const float* __restrict__ bv)
{
    __shared__ float xs[32 * 32];       // [c][n]
    __shared__ float ws[320 * 33];      // [d][c], pad 33 -> conflict-free

    const int tid  = threadIdx.x;
    const int b    = blockIdx.y;
    const int n0   = blockIdx.x * 32;
    const int dg   = tid & 63;          // d slot (d = dg + 64*s)
    const int ngrp = tid >> 6;          // owns n = ngrp*8 .. +7

    float acc[5][8];
#pragma unroll
    for (int s = 0; s < 5; s++)
#pragma unroll
        for (int i = 0; i < 8; i++) acc[s][i] = 0.f;

    for (int c0 = 0; c0 < CC; c0 += 32) {
        // load x chunk [32 c][32 n], coalesced
#pragma unroll
        for (int k = 0; k < 4; k++) {
            int idx = tid + k * 256;
            int c = idx >> 5, j = idx & 31;
            xs[idx] = x[((size_t)(b * CC + c0 + c)) * NN + n0 + j];
        }
        // load W chunk [320 d][32 c], coalesced rows
#pragma unroll
        for (int k = 0; k < 40; k++) {
            int idx = tid + k * 256;
            int d = idx >> 5, cc = idx & 31;
            const float* row = (d < 32) ? (Wq + d * CC)
                             : (d < 64) ? (Wk + (d - 32) * CC)
                                        : (Wv + (d - 64) * CC);
            ws[d * 33 + cc] = row[c0 + cc];
        }
        __syncthreads();

#pragma unroll 8
        for (int cc2 = 0; cc2 < 32; cc2++) {
            float xv[8];
#pragma unroll
            for (int i = 0; i < 8; i++) xv[i] = xs[cc2 * 32 + ngrp * 8 + i];
#pragma unroll
            for (int s = 0; s < 5; s++) {
                float wv = ws[(dg + 64 * s) * 33 + cc2];
#pragma unroll
                for (int i = 0; i < 8; i++) acc[s][i] += wv * xv[i];
            }
        }
        __syncthreads();
    }

    // bias + writeout to scratch
#pragma unroll
    for (int s = 0; s < 5; s++) {
        int d = dg + 64 * s;
        float bias = (d < 32) ? bq[d] : (d < 64) ? bk[d - 32] : bv[d - 64];
#pragma unroll
        for (int i = 0; i < 8; i++) {
            int n = n0 + ngrp * 8 + i;
            float val = acc[s][i] + bias;
            if (d < 32)       g_q[((size_t)(b * NN + n)) * DD + d]        = val;
            else if (d < 64)  g_k[((size_t)(b * NN + n)) * DD + (d - 32)] = val;
            else              g_v[((size_t)(b * NN + n)) * CC + (d - 64)] = val;
        }
    }
}

// ---------------------------------------------------------------------------
// Kernel 2: flash attention, fp32.
// Block = (b, 64 query rows). Per 64-key tile: scores (4x4 microtile/thread),
// online softmax (64 row threads), PV accumulate (8m x 8c register tile,
// p broadcast within warp). Epilogue stages out-tile through smem for
// coalesced writes fused with gamma*out + x.
// Dynamic smem (floats):
//   qs 64*36=2304 | ks 2304 | vs/cs 16448 | ps 64*65=4160 | stats 192
// ---------------------------------------------------------------------------
__global__ __launch_bounds__(256, 2) void attn_kernel(
    const float* __restrict__ x, const float* __restrict__ gamma,
    float* __restrict__ out)
{
    extern __shared__ float sm[];
    float* qs   = sm;             // [m][36]
    float* ks   = sm + 2304;      // [n][36]
    float* vs   = sm + 4608;      // [n][256] (16448 floats reserved for cs reuse)
    float* ps   = sm + 21056;     // [m][65]
    float* m_s  = sm + 25216;     // [64]
    float* l_s  = m_s + 64;
    float* al_s = l_s + 64;

    const int tid = threadIdx.x;
    const int b   = blockIdx.y;
    const int n0  = blockIdx.x * BM;

    // load q tile [64][32]
#pragma unroll
    for (int k = 0; k < 8; k++) {
        int idx = tid + k * 256;
        int m = idx >> 5, d = idx & 31;
        qs[m * 36 + d] = g_q[((size_t)(b * NN + n0 + m)) * DD + d];
    }
    if (tid < 64) { m_s[tid] = -INFINITY; l_s[tid] = 0.f; }

    float acc[8][8];
#pragma unroll
    for (int i = 0; i < 8; i++)
#pragma unroll
        for (int j = 0; j < 8; j++) acc[i][j] = 0.f;

    const int mg = tid >> 5;   // warp id: owns m rows mg*8 + i
    const int cg = tid & 31;   // owns c cols cg*8 + j
    const int tm = tid >> 4;   // scores: 4 m rows tm*4..
    const int tn = tid & 15;   // scores: 4 n cols tn*4..

    const float4* gv4 = (const float4*)g_v;
    float4* vs4       = (float4*)vs;
    const float4* qs4 = (const float4*)qs;
    const float4* ks4 = (const float4*)ks;

    for (int t = 0; t < NN / BN; t++) {
        const int nt = t * BN;
        __syncthreads();  // previous PV done reading vs/ps

        // load k tile [64][32]
#pragma unroll
        for (int k = 0; k < 8; k++) {
            int idx = tid + k * 256;
            int nn = idx >> 5, d = idx & 31;
            ks[nn * 36 + d] = g_k[((size_t)(b * NN + nt + nn)) * DD + d];
        }
        // load v tile [64][256] via float4
#pragma unroll
        for (int k = 0; k < 16; k++) {
            int idx = tid + k * 256;
            vs4[idx] = gv4[((size_t)(b * NN + nt)) * 64 + idx];
        }
        __syncthreads();

        // ---- scores: S = q k^T (4x4 microtile per thread) ----
        float sacc[4][4];
#pragma unroll
        for (int i = 0; i < 4; i++)
#pragma unroll
            for (int j = 0; j < 4; j++) sacc[i][j] = 0.f;

#pragma unroll
        for (int d4 = 0; d4 < 8; d4++) {
            float4 qv[4], kv[4];
#pragma unroll
            for (int i = 0; i < 4; i++) qv[i] = qs4[(tm * 4 + i) * 9 + d4];
#pragma unroll
            for (int j = 0; j < 4; j++) kv[j] = ks4[(tn * 4 + j) * 9 + d4];
#pragma unroll
            for (int i = 0; i < 4; i++)
#pragma unroll
                for (int j = 0; j < 4; j++) {
                    sacc[i][j] += qv[i].x * kv[j].x;
                    sacc[i][j] += qv[i].y * kv[j].y;
                    sacc[i][j] += qv[i].z * kv[j].z;
                    sacc[i][j] += qv[i].w * kv[j].w;
                }
        }
#pragma unroll
        for (int i = 0; i < 4; i++)
#pragma unroll
            for (int j = 0; j < 4; j++)
                ps[(tm * 4 + i) * 65 + tn * 4 + j] = sacc[i][j];
        __syncthreads();

        // ---- online softmax (one thread per row) ----
        if (tid < 64) {
            float mold = m_s[tid];
            float mx = mold;
#pragma unroll 8
            for (int n = 0; n < BN; n++) mx = fmaxf(mx, ps[tid * 65 + n]);
            float sum = 0.f;
#pragma unroll 8
            for (int n = 0; n < BN; n++) {
                float e = __expf(ps[tid * 65 + n] - mx);
                ps[tid * 65 + n] = e;
                sum += e;
            }
            float a = __expf(mold - mx);
            l_s[tid]  = l_s[tid] * a + sum;
            m_s[tid]  = mx;
            al_s[tid] = a;
        }
        __syncthreads();

        // ---- PV accumulate ----
#pragma unroll
        for (int i = 0; i < 8; i++) {
            float a = al_s[mg * 8 + i];
#pragma unroll
            for (int j = 0; j < 8; j++) acc[i][j] *= a;
        }
#pragma unroll 2
        for (int n = 0; n < BN; n++) {
            float4 v0 = vs4[n * 64 + cg * 2];
            float4 v1 = vs4[n * 64 + cg * 2 + 1];
#pragma unroll
            for (int i = 0; i < 8; i++) {
                float p = ps[(mg * 8 + i) * 65 + n];
                acc[i][0] += p * v0.x;  acc[i][1] += p * v0.y;
                acc[i][2] += p * v0.z;  acc[i][3] += p * v0.w;
                acc[i][4] += p * v1.x;  acc[i][5] += p * v1.y;
                acc[i][6] += p * v1.z;  acc[i][7] += p * v1.w;
            }
        }
    }

    // ---- epilogue: normalize, gamma, + x, coalesced write ----
    __syncthreads();
    const float g0 = gamma[0];
    float* cs = vs;  // reuse region as [m][257]
#pragma unroll
    for (int i = 0; i < 8; i++) {
        float sc = g0 / l_s[mg * 8 + i];
#pragma unroll
        for (int j = 0; j < 8; j++)
            cs[(mg * 8 + i) * 257 + cg * 8 + j] = acc[i][j] * sc;
    }
    __syncthreads();

    const float4* x4 = (const float4*)x;
    float4* o4       = (float4*)out;
#pragma unroll
    for (int r = 0; r < 16; r++) {
        int idx = tid + r * 256;
        int c  = idx >> 4;
        int mq = (idx & 15) * 4;
        size_t gi = (((size_t)(b * CC + c)) * NN + n0 + mq) >> 2;
        float4 xv = x4[gi];
        float4 o;
        o.x = cs[(mq + 0) * 257 + c] + xv.x;
        o.y = cs[(mq + 1) * 257 + c] + xv.y;
        o.z = cs[(mq + 2) * 257 + c] + xv.z;
        o.w = cs[(mq + 3) * 257 + c] + xv.w;
        o4[gi] = o;
    }
}

// ---------------------------------------------------------------------------
extern "C" void kernel_launch(void* const* d_in, const int* in_sizes, int n_in,
                              void* d_out, int out_size)
{
    const float* x     = (const float*)d_in[0];
    const float* Wq    = (const float*)d_in[1];
    const float* bq    = (const float*)d_in[2];
    const float* Wk    = (const float*)d_in[3];
    const float* bk    = (const float*)d_in[4];
    const float* Wv    = (const float*)d_in[5];
    const float* bv    = (const float*)d_in[6];
    const float* gamma = (const float*)d_in[7];
    float* out = (float*)d_out;

    (void)in_sizes; (void)n_in; (void)out_size;

    cudaFuncSetAttribute(attn_kernel,
                         cudaFuncAttributeMaxDynamicSharedMemorySize, 101632);

    proj_kernel<<<dim3(NN / 32, BATCH), 256>>>(x, Wq, bq, Wk, bk, Wv, bv);
    attn_kernel<<<dim3(NN / BM, BATCH), 256, 101632>>>(x, gamma, out);
}

// round 3
// speedup vs baseline: 2.1780x; 2.1780x over previous
#include <cuda_runtime.h>
#include <math.h>
#include <stdint.h>

#define CC    256
#define NN    4096
#define DD    32
#define BATCH 8
#define BM    64
#define BN    64
#define L2E   1.4426950408889634f

// Scratch (q/k tf32-rounded, [b][n][32]; v fp32 [b][n][256])
__device__ float g_q[BATCH * NN * DD];
__device__ float g_k[BATCH * NN * DD];
__device__ float g_v[(size_t)BATCH * NN * CC];

__device__ __forceinline__ float to_tf32(float x) {
    uint32_t u;
    asm("cvt.rna.tf32.f32 %0, %1;" : "=r"(u) : "f"(x));
    return __uint_as_float(u);
}

// D += A(16x8) * B(8x8), tf32 inputs, f32 accum
__device__ __forceinline__ void mma_tf32(float d[4], const float a[4], const float b[2]) {
    asm volatile(
        "mma.sync.aligned.m16n8k8.row.col.f32.tf32.tf32.f32 "
        "{%0,%1,%2,%3}, {%4,%5,%6,%7}, {%8,%9}, {%0,%1,%2,%3};"
        : "+f"(d[0]), "+f"(d[1]), "+f"(d[2]), "+f"(d[3])
        : "r"(__float_as_uint(a[0])), "r"(__float_as_uint(a[1])),
          "r"(__float_as_uint(a[2])), "r"(__float_as_uint(a[3])),
          "r"(__float_as_uint(b[0])), "r"(__float_as_uint(b[1])));
}

// ---------------------------------------------------------------------------
// Kernel 1: fused QKV projection (unchanged math; q/k written tf32-rounded).
// ---------------------------------------------------------------------------
__global__ __launch_bounds__(256) void proj_kernel(
    const float* __restrict__ x,
    const float* __restrict__ Wq, const float* __restrict__ bq,
    const float* __restrict__ Wk, const float* __restrict__ bk,
    const float* __restrict__ Wv, const float* __restrict__ bv)
{
    __shared__ float xs[32 * 32];
    __shared__ float ws[320 * 33];

    const int tid  = threadIdx.x;
    const int b    = blockIdx.y;
    const int n0   = blockIdx.x * 32;
    const int dg   = tid & 63;
    const int ngrp = tid >> 6;

    float acc[5][8];
#pragma unroll
    for (int s = 0; s < 5; s++)
#pragma unroll
        for (int i = 0; i < 8; i++) acc[s][i] = 0.f;

    for (int c0 = 0; c0 < CC; c0 += 32) {
#pragma unroll
        for (int k = 0; k < 4; k++) {
            int idx = tid + k * 256;
            int c = idx >> 5, j = idx & 31;
            xs[idx] = x[((size_t)(b * CC + c0 + c)) * NN + n0 + j];
        }
#pragma unroll
        for (int k = 0; k < 40; k++) {
            int idx = tid + k * 256;
            int d = idx >> 5, cc = idx & 31;
            const float* row = (d < 32) ? (Wq + d * CC)
                             : (d < 64) ? (Wk + (d - 32) * CC)
                                        : (Wv + (d - 64) * CC);
            ws[d * 33 + cc] = row[c0 + cc];
        }
        __syncthreads();

#pragma unroll 8
        for (int cc2 = 0; cc2 < 32; cc2++) {
            float xv[8];
#pragma unroll
            for (int i = 0; i < 8; i++) xv[i] = xs[cc2 * 32 + ngrp * 8 + i];
#pragma unroll
            for (int s = 0; s < 5; s++) {
                float wv = ws[(dg + 64 * s) * 33 + cc2];
#pragma unroll
                for (int i = 0; i < 8; i++) acc[s][i] += wv * xv[i];
            }
        }
        __syncthreads();
    }

#pragma unroll
    for (int s = 0; s < 5; s++) {
        int d = dg + 64 * s;
        float bias = (d < 32) ? bq[d] : (d < 64) ? bk[d - 32] : bv[d - 64];
#pragma unroll
        for (int i = 0; i < 8; i++) {
            int n = n0 + ngrp * 8 + i;
            float val = acc[s][i] + bias;
            if (d < 32)       g_q[((size_t)(b * NN + n)) * DD + d]        = to_tf32(val);
            else if (d < 64)  g_k[((size_t)(b * NN + n)) * DD + (d - 32)] = to_tf32(val);
            else              g_v[((size_t)(b * NN + n)) * CC + (d - 64)] = val;
        }
    }
}

// ---------------------------------------------------------------------------
// Kernel 2: FlashAttention-2 on tf32 mma.sync.m16n8k8.
// Block: 64 queries, 8 warps = 4 m-bands(16 rows) x 2 c-halves(128 cols).
// Each warp computes full S row-band 16x64 (duplicated across the c-pair),
// online softmax in registers (quad shuffles), P re-shaped to A-fragments
// via shuffles, PV accumulated in f32 fragments.
// Smem (floats): qs[64][36]=2304 | ks[64][36]=2304 | vs[64][260]=16640
//   (vs region reused as cs[64][257] in the epilogue)
// ---------------------------------------------------------------------------
__global__ __launch_bounds__(256, 1) void attn_kernel(
    const float* __restrict__ x, const float* __restrict__ gamma,
    float* __restrict__ out)
{
    extern __shared__ float sm[];
    float* qs = sm;           // [m][36]
    float* ks = sm + 2304;    // [n][36]
    float* vs = sm + 4608;    // [k][260]

    const int tid  = threadIdx.x;
    const int b    = blockIdx.y;
    const int n0   = blockIdx.x * BM;
    const int wid  = tid >> 5;
    const int lane = tid & 31;
    const int m0   = (wid >> 1) * 16;     // m-band
    const int cb   = (wid & 1) * 128;     // c-half
    const int r    = lane >> 2;           // group id (row)
    const int q    = lane & 3;            // thread-in-group

    // ---- stage Q tile ----
#pragma unroll
    for (int k = 0; k < 2; k++) {
        int idx = tid + k * 256;
        int m = idx >> 3, d4 = idx & 7;
        *(float4*)&qs[m * 36 + d4 * 4] =
            *(const float4*)&g_q[((size_t)(b * NN + n0 + m)) * DD + d4 * 4];
    }
    __syncthreads();

    // ---- Q A-fragments (loop-invariant) ----
    float qa[4][4];
#pragma unroll
    for (int kc = 0; kc < 4; kc++) {
        qa[kc][0] = qs[(m0 + r)     * 36 + kc * 8 + q];
        qa[kc][1] = qs[(m0 + r + 8) * 36 + kc * 8 + q];
        qa[kc][2] = qs[(m0 + r)     * 36 + kc * 8 + q + 4];
        qa[kc][3] = qs[(m0 + r + 8) * 36 + kc * 8 + q + 4];
    }

    float o[16][4];
#pragma unroll
    for (int cf = 0; cf < 16; cf++)
#pragma unroll
        for (int j = 0; j < 4; j++) o[cf][j] = 0.f;

    float mrow0 = -INFINITY, mrow1 = -INFINITY;
    float lrow0 = 0.f, lrow1 = 0.f;

    const int sbase = lane & ~3;
    const int s0 = sbase + (q >> 1);
    const int s2 = s0 + 2;
    const bool esel = (q & 1);

    for (int t = 0; t < NN / BN; t++) {
        const int nt = t * BN;
        __syncthreads();   // previous tile's vs/ks reads done

        // ---- stage K tile [64][36] ----
#pragma unroll
        for (int k = 0; k < 2; k++) {
            int idx = tid + k * 256;
            int n = idx >> 3, d4 = idx & 7;
            *(float4*)&ks[n * 36 + d4 * 4] =
                *(const float4*)&g_k[((size_t)(b * NN + nt + n)) * DD + d4 * 4];
        }
        // ---- stage V tile [64][260] (row-major keys, coalesced) ----
#pragma unroll
        for (int k2 = 0; k2 < 16; k2++) {
            int idx = tid + k2 * 256;
            int n = idx >> 6, c4 = idx & 63;
            *(float4*)&vs[n * 260 + c4 * 4] =
                *(const float4*)&g_v[((size_t)(b * NN + nt + n)) * CC + c4 * 4];
        }
        __syncthreads();

        // ---- S = Q K^T : 16x64 per warp ----
        float sf[8][4];
#pragma unroll
        for (int nf = 0; nf < 8; nf++) {
            sf[nf][0] = sf[nf][1] = sf[nf][2] = sf[nf][3] = 0.f;
#pragma unroll
            for (int kc = 0; kc < 4; kc++) {
                float kb[2];
                kb[0] = ks[(nf * 8 + r) * 36 + kc * 8 + q];
                kb[1] = ks[(nf * 8 + r) * 36 + kc * 8 + q + 4];
                mma_tf32(sf[nf], qa[kc], kb);
            }
        }

        // ---- online softmax (registers + quad shuffles) ----
        float mx0 = -INFINITY, mx1 = -INFINITY;
#pragma unroll
        for (int nf = 0; nf < 8; nf++) {
            mx0 = fmaxf(mx0, fmaxf(sf[nf][0], sf[nf][1]));
            mx1 = fmaxf(mx1, fmaxf(sf[nf][2], sf[nf][3]));
        }
        mx0 = fmaxf(mx0, __shfl_xor_sync(0xffffffffu, mx0, 1));
        mx0 = fmaxf(mx0, __shfl_xor_sync(0xffffffffu, mx0, 2));
        mx1 = fmaxf(mx1, __shfl_xor_sync(0xffffffffu, mx1, 1));
        mx1 = fmaxf(mx1, __shfl_xor_sync(0xffffffffu, mx1, 2));

        float mnew0 = fmaxf(mrow0, mx0);
        float mnew1 = fmaxf(mrow1, mx1);
        float al0 = exp2f((mrow0 - mnew0) * L2E);
        float al1 = exp2f((mrow1 - mnew1) * L2E);
        mrow0 = mnew0; mrow1 = mnew1;
        const float mb0 = mnew0 * L2E, mb1 = mnew1 * L2E;

        float sum0 = 0.f, sum1 = 0.f;
#pragma unroll
        for (int nf = 0; nf < 8; nf++) {
            sf[nf][0] = exp2f(fmaf(sf[nf][0], L2E, -mb0));
            sf[nf][1] = exp2f(fmaf(sf[nf][1], L2E, -mb0));
            sf[nf][2] = exp2f(fmaf(sf[nf][2], L2E, -mb1));
            sf[nf][3] = exp2f(fmaf(sf[nf][3], L2E, -mb1));
            sum0 += sf[nf][0] + sf[nf][1];
            sum1 += sf[nf][2] + sf[nf][3];
        }
        sum0 += __shfl_xor_sync(0xffffffffu, sum0, 1);
        sum0 += __shfl_xor_sync(0xffffffffu, sum0, 2);
        sum1 += __shfl_xor_sync(0xffffffffu, sum1, 1);
        sum1 += __shfl_xor_sync(0xffffffffu, sum1, 2);
        lrow0 = lrow0 * al0 + sum0;
        lrow1 = lrow1 * al1 + sum1;

        // rescale O
#pragma unroll
        for (int cf = 0; cf < 16; cf++) {
            o[cf][0] *= al0; o[cf][1] *= al0;
            o[cf][2] *= al1; o[cf][3] *= al1;
        }

        // ---- PV: reshape P frags -> A frags via shuffles, then mma ----
#pragma unroll
        for (int kc = 0; kc < 8; kc++) {
            float a[4];
            {
                float t0 = __shfl_sync(0xffffffffu, sf[kc][0], s0);
                float t1 = __shfl_sync(0xffffffffu, sf[kc][1], s0);
                a[0] = esel ? t1 : t0;
                float t2 = __shfl_sync(0xffffffffu, sf[kc][2], s0);
                float t3 = __shfl_sync(0xffffffffu, sf[kc][3], s0);
                a[1] = esel ? t3 : t2;
                float u0 = __shfl_sync(0xffffffffu, sf[kc][0], s2);
                float u1 = __shfl_sync(0xffffffffu, sf[kc][1], s2);
                a[2] = esel ? u1 : u0;
                float u2 = __shfl_sync(0xffffffffu, sf[kc][2], s2);
                float u3 = __shfl_sync(0xffffffffu, sf[kc][3], s2);
                a[3] = esel ? u3 : u2;
            }
#pragma unroll
            for (int cf = 0; cf < 16; cf++) {
                float vb[2];
                vb[0] = vs[(kc * 8 + q)     * 260 + cb + cf * 8 + r];
                vb[1] = vs[(kc * 8 + q + 4) * 260 + cb + cf * 8 + r];
                mma_tf32(o[cf], a, vb);
            }
        }
    }

    // ---- epilogue: normalize + gamma, stage to smem, coalesced out ----
    __syncthreads();
    const float g0 = __ldg(gamma);
    const float sc0 = g0 / lrow0;
    const float sc1 = g0 / lrow1;
    float* cs = vs;   // [m][257]
#pragma unroll
    for (int cf = 0; cf < 16; cf++) {
        int c = cb + cf * 8 + 2 * q;
        cs[(m0 + r)     * 257 + c]     = o[cf][0] * sc0;
        cs[(m0 + r)     * 257 + c + 1] = o[cf][1] * sc0;
        cs[(m0 + r + 8) * 257 + c]     = o[cf][2] * sc1;
        cs[(m0 + r + 8) * 257 + c + 1] = o[cf][3] * sc1;
    }
    __syncthreads();

    const float4* x4 = (const float4*)x;
    float4* o4       = (float4*)out;
#pragma unroll
    for (int r2 = 0; r2 < 16; r2++) {
        int idx = tid + r2 * 256;
        int c  = idx >> 4;
        int mq = (idx & 15) * 4;
        size_t gi = (((size_t)(b * CC + c)) * NN + n0 + mq) >> 2;
        float4 xv = x4[gi];
        float4 ov;
        ov.x = cs[(mq + 0) * 257 + c] + xv.x;
        ov.y = cs[(mq + 1) * 257 + c] + xv.y;
        ov.z = cs[(mq + 2) * 257 + c] + xv.z;
        ov.w = cs[(mq + 3) * 257 + c] + xv.w;
        o4[gi] = ov;
    }
}

// ---------------------------------------------------------------------------
extern "C" void kernel_launch(void* const* d_in, const int* in_sizes, int n_in,
                              void* d_out, int out_size)
{
    const float* x     = (const float*)d_in[0];
    const float* Wq    = (const float*)d_in[1];
    const float* bq    = (const float*)d_in[2];
    const float* Wk    = (const float*)d_in[3];
    const float* bk    = (const float*)d_in[4];
    const float* Wv    = (const float*)d_in[5];
    const float* bv    = (const float*)d_in[6];
    const float* gamma = (const float*)d_in[7];
    float* out = (float*)d_out;

    (void)in_sizes; (void)n_in; (void)out_size;

    const int smem_bytes = (2304 + 2304 + 64 * 260) * 4;  // 84992
    cudaFuncSetAttribute(attn_kernel,
                         cudaFuncAttributeMaxDynamicSharedMemorySize, smem_bytes);

    proj_kernel<<<dim3(NN / 32, BATCH), 256>>>(x, Wq, bq, Wk, bk, Wv, bv);
    attn_kernel<<<dim3(NN / BM, BATCH), 256, smem_bytes>>>(x, gamma, out);
}

// round 6
// speedup vs baseline: 4.5169x; 2.0739x over previous
#include <cuda_runtime.h>
#include <cuda_fp16.h>
#include <math.h>
#include <stdint.h>

#define CC    256
#define NN    4096
#define DD    32
#define BATCH 8
#define BM    64
#define BN    64
#define NTILES (NN/BN)
#define L2E   1.4426950408889634f

// Scratch: q/k tf32-rounded [b][n][32] fp32; v fp16 c-major [b][c][n]
__device__ float g_q[BATCH * NN * DD];
__device__ float g_k[BATCH * NN * DD];
__device__ __align__(16) __half g_vh[(size_t)BATCH * CC * NN];

__device__ __forceinline__ float to_tf32(float x) {
    uint32_t u;
    asm("cvt.rna.tf32.f32 %0, %1;" : "=r"(u) : "f"(x));
    return __uint_as_float(u);
}
__device__ __forceinline__ uint32_t smem_u32(const void* p) {
    uint32_t a;
    asm("{ .reg .u64 t; cvta.to.shared.u64 t, %1; cvt.u32.u64 %0, t; }"
        : "=r"(a) : "l"(p));
    return a;
}
__device__ __forceinline__ uint32_t f2h2(float lo, float hi) {
    __half2 h = __floats2half2_rn(lo, hi);
    return *(uint32_t*)&h;
}

// D += A(16x8,tf32) * B(8x8,tf32)
__device__ __forceinline__ void mma_tf32(float d[4], const float a[4], const float b[2]) {
    asm volatile(
        "mma.sync.aligned.m16n8k8.row.col.f32.tf32.tf32.f32 "
        "{%0,%1,%2,%3}, {%4,%5,%6,%7}, {%8,%9}, {%0,%1,%2,%3};"
        : "+f"(d[0]), "+f"(d[1]), "+f"(d[2]), "+f"(d[3])
        : "r"(__float_as_uint(a[0])), "r"(__float_as_uint(a[1])),
          "r"(__float_as_uint(a[2])), "r"(__float_as_uint(a[3])),
          "r"(__float_as_uint(b[0])), "r"(__float_as_uint(b[1])));
}
// D += A(16x16,f16) * B(16x8,f16), f32 accum
__device__ __forceinline__ void mma_f16(float d[4], uint32_t a0, uint32_t a1,
                                        uint32_t a2, uint32_t a3,
                                        uint32_t b0, uint32_t b1) {
    asm volatile(
        "mma.sync.aligned.m16n8k16.row.col.f32.f16.f16.f32 "
        "{%0,%1,%2,%3}, {%4,%5,%6,%7}, {%8,%9}, {%0,%1,%2,%3};"
        : "+f"(d[0]), "+f"(d[1]), "+f"(d[2]), "+f"(d[3])
        : "r"(a0), "r"(a1), "r"(a2), "r"(a3), "r"(b0), "r"(b1));
}

#define CP16(dst, src) \
    asm volatile("cp.async.cg.shared.global [%0], [%1], 16;" :: "r"(dst), "l"(src))
#define CP_COMMIT() asm volatile("cp.async.commit_group;" ::: "memory")
#define CP_WAIT1()  asm volatile("cp.async.wait_group 1;" ::: "memory")

// ---------------- smem layout (bytes) ----------------
// qs: [64][36] f32                 9216
// ks: 2 x [64][36] f32            18432
// vs: 2 x [256][72] f16 (144B/row) 73728   (reused as cs [64][257] f32 in epilogue)
#define OFF_Q 0
#define OFF_K 9216
#define OFF_V 27648
#define SMEM_TOTAL (27648 + 2 * 36864)

// ---------------------------------------------------------------------------
// Kernel 1: fused QKV projection; q/k tf32-rounded [b][n][32], v fp16 [b][c][n]
// ---------------------------------------------------------------------------
__global__ __launch_bounds__(256) void proj_kernel(
    const float* __restrict__ x,
    const float* __restrict__ Wq, const float* __restrict__ bq,
    const float* __restrict__ Wk, const float* __restrict__ bk,
    const float* __restrict__ Wv, const float* __restrict__ bv)
{
    __shared__ float xs[32 * 32];
    __shared__ float ws[320 * 33];   // reused as vt[256][33]

    const int tid  = threadIdx.x;
    const int b    = blockIdx.y;
    const int n0   = blockIdx.x * 32;
    const int dg   = tid & 63;
    const int ngrp = tid >> 6;

    float acc[5][8];
#pragma unroll
    for (int s = 0; s < 5; s++)
#pragma unroll
        for (int i = 0; i < 8; i++) acc[s][i] = 0.f;

    for (int c0 = 0; c0 < CC; c0 += 32) {
#pragma unroll
        for (int k = 0; k < 4; k++) {
            int idx = tid + k * 256;
            int c = idx >> 5, j = idx & 31;
            xs[idx] = x[((size_t)(b * CC + c0 + c)) * NN + n0 + j];
        }
#pragma unroll
        for (int k = 0; k < 40; k++) {
            int idx = tid + k * 256;
            int d = idx >> 5, cc = idx & 31;
            const float* row = (d < 32) ? (Wq + d * CC)
                             : (d < 64) ? (Wk + (d - 32) * CC)
                                        : (Wv + (d - 64) * CC);
            ws[d * 33 + cc] = row[c0 + cc];
        }
        __syncthreads();

#pragma unroll 8
        for (int cc2 = 0; cc2 < 32; cc2++) {
            float xv[8];
#pragma unroll
            for (int i = 0; i < 8; i++) xv[i] = xs[cc2 * 32 + ngrp * 8 + i];
#pragma unroll
            for (int s = 0; s < 5; s++) {
                float wv = ws[(dg + 64 * s) * 33 + cc2];
#pragma unroll
                for (int i = 0; i < 8; i++) acc[s][i] += wv * xv[i];
            }
        }
        __syncthreads();
    }

    // q/k writeout (tf32 rounded)
    {
        int d = dg;
        float bias = (d < 32) ? bq[d] : bk[d - 32];
#pragma unroll
        for (int i = 0; i < 8; i++) {
            int n = n0 + ngrp * 8 + i;
            float val = to_tf32(acc[0][i] + bias);
            if (d < 32) g_q[((size_t)(b * NN + n)) * DD + d] = val;
            else        g_k[((size_t)(b * NN + n)) * DD + (d - 32)] = val;
        }
    }
    // v: transpose through smem -> [b][c][n] fp16
    float* vt = ws;
#pragma unroll
    for (int s = 1; s < 5; s++) {
        int c = dg + 64 * (s - 1);
        float bias = bv[c];
#pragma unroll
        for (int i = 0; i < 8; i++)
            vt[c * 33 + ngrp * 8 + i] = acc[s][i] + bias;
    }
    __syncthreads();
#pragma unroll
    for (int it = 0; it < 4; it++) {
        int lin = tid + it * 256;
        int c = lin >> 2, nq = lin & 3;
        uint32_t hh[4];
#pragma unroll
        for (int j = 0; j < 4; j++)
            hh[j] = f2h2(vt[c * 33 + nq * 8 + 2 * j], vt[c * 33 + nq * 8 + 2 * j + 1]);
        *(uint4*)&g_vh[((size_t)(b * CC + c)) * NN + n0 + nq * 8] =
            make_uint4(hh[0], hh[1], hh[2], hh[3]);
    }
}

// ---------------------------------------------------------------------------
// Kernel 2: FlashAttention-2, S in tf32 mma, PV in fp16 m16n8k16.
// 8 warps = 4 m-bands(16) x 2 c-halves(128). Double-buffered cp.async K/V.
// ---------------------------------------------------------------------------
__device__ __forceinline__ void stage_k(uint32_t sb, int b, int nt, int bi, int tid)
{
    const uint32_t base = sb + OFF_K + bi * 9216;
#pragma unroll
    for (int it = 0; it < 2; it++) {
        int idx = tid + it * 256;
        int n = idx >> 3, d4 = idx & 7;
        CP16(base + (uint32_t)(n * 144 + d4 * 16),
             g_k + ((size_t)(b * NN + nt + n)) * DD + d4 * 4);
    }
}
__device__ __forceinline__ void stage_v(uint32_t sb, int b, int nt, int bi, int tid)
{
    const uint32_t base = sb + OFF_V + bi * 36864;
#pragma unroll
    for (int it = 0; it < 8; it++) {
        int idx = tid + it * 256;
        int c = idx >> 3, ch = idx & 7;
        CP16(base + (uint32_t)(c * 144 + ch * 16),
             g_vh + ((size_t)(b * CC + c)) * NN + nt + ch * 8);
    }
}

__global__ __launch_bounds__(256, 1) void attn_kernel(
    const float* __restrict__ x, const float* __restrict__ gamma,
    float* __restrict__ out)
{
    extern __shared__ char smem[];
    const uint32_t sb = smem_u32(smem);
    float* qs = (float*)(smem + OFF_Q);   // [m][36]

    const int tid  = threadIdx.x;
    const int b    = blockIdx.y;
    const int n0   = blockIdx.x * BM;
    const int wid  = tid >> 5;
    const int lane = tid & 31;
    const int m0   = (wid >> 1) * 16;     // m-band
    const int cb   = (wid & 1) * 128;     // c-half
    const int r    = lane >> 2;
    const int q    = lane & 3;

    // prefetch tiles 0 and 1
    stage_k(sb, b, 0, 0, tid);  stage_v(sb, b, 0, 0, tid);  CP_COMMIT();
    stage_k(sb, b, BN, 1, tid); stage_v(sb, b, BN, 1, tid); CP_COMMIT();

    // stage Q tile (plain loads)
#pragma unroll
    for (int k = 0; k < 2; k++) {
        int idx = tid + k * 256;
        int m = idx >> 3, d4 = idx & 7;
        *(float4*)&qs[m * 36 + d4 * 4] =
            *(const float4*)&g_q[((size_t)(b * NN + n0 + m)) * DD + d4 * 4];
    }
    __syncthreads();

    // Q A-fragments (loop-invariant)
    float qa[4][4];
#pragma unroll
    for (int kc = 0; kc < 4; kc++) {
        qa[kc][0] = qs[(m0 + r)     * 36 + kc * 8 + q];
        qa[kc][1] = qs[(m0 + r + 8) * 36 + kc * 8 + q];
        qa[kc][2] = qs[(m0 + r)     * 36 + kc * 8 + q + 4];
        qa[kc][3] = qs[(m0 + r + 8) * 36 + kc * 8 + q + 4];
    }

    float o[16][4];
#pragma unroll
    for (int cf = 0; cf < 16; cf++)
#pragma unroll
        for (int j = 0; j < 4; j++) o[cf][j] = 0.f;

    float mrow0 = -INFINITY, mrow1 = -INFINITY;
    float lrow0 = 0.f, lrow1 = 0.f;

    for (int t = 0; t < NTILES; t++) {
        const int bi = t & 1;
        CP_WAIT1();
        __syncthreads();

        const float*    ksb  = (const float*)(smem + OFF_K + bi * 9216);
        const uint32_t* vs32 = (const uint32_t*)(smem + OFF_V + bi * 36864);

        // ---- S = Q K^T : 16x64 per warp (tf32) ----
        float sf[8][4];
#pragma unroll
        for (int nf = 0; nf < 8; nf++) {
            sf[nf][0] = sf[nf][1] = sf[nf][2] = sf[nf][3] = 0.f;
#pragma unroll
            for (int kc = 0; kc < 4; kc++) {
                float kb[2];
                kb[0] = ksb[(nf * 8 + r) * 36 + kc * 8 + q];
                kb[1] = ksb[(nf * 8 + r) * 36 + kc * 8 + q + 4];
                mma_tf32(sf[nf], qa[kc], kb);
            }
        }

        // ---- online softmax (registers + quad shuffles) ----
        float mx0 = -INFINITY, mx1 = -INFINITY;
#pragma unroll
        for (int nf = 0; nf < 8; nf++) {
            mx0 = fmaxf(mx0, fmaxf(sf[nf][0], sf[nf][1]));
            mx1 = fmaxf(mx1, fmaxf(sf[nf][2], sf[nf][3]));
        }
        mx0 = fmaxf(mx0, __shfl_xor_sync(0xffffffffu, mx0, 1));
        mx0 = fmaxf(mx0, __shfl_xor_sync(0xffffffffu, mx0, 2));
        mx1 = fmaxf(mx1, __shfl_xor_sync(0xffffffffu, mx1, 1));
        mx1 = fmaxf(mx1, __shfl_xor_sync(0xffffffffu, mx1, 2));

        float mnew0 = fmaxf(mrow0, mx0);
        float mnew1 = fmaxf(mrow1, mx1);
        float al0 = exp2f((mrow0 - mnew0) * L2E);
        float al1 = exp2f((mrow1 - mnew1) * L2E);
        mrow0 = mnew0; mrow1 = mnew1;
        const float mb0 = mnew0 * L2E, mb1 = mnew1 * L2E;

        float sum0 = 0.f, sum1 = 0.f;
#pragma unroll
        for (int nf = 0; nf < 8; nf++) {
            sf[nf][0] = exp2f(fmaf(sf[nf][0], L2E, -mb0));
            sf[nf][1] = exp2f(fmaf(sf[nf][1], L2E, -mb0));
            sf[nf][2] = exp2f(fmaf(sf[nf][2], L2E, -mb1));
            sf[nf][3] = exp2f(fmaf(sf[nf][3], L2E, -mb1));
            sum0 += sf[nf][0] + sf[nf][1];
            sum1 += sf[nf][2] + sf[nf][3];
        }
        sum0 += __shfl_xor_sync(0xffffffffu, sum0, 1);
        sum0 += __shfl_xor_sync(0xffffffffu, sum0, 2);
        sum1 += __shfl_xor_sync(0xffffffffu, sum1, 1);
        sum1 += __shfl_xor_sync(0xffffffffu, sum1, 2);
        lrow0 = lrow0 * al0 + sum0;
        lrow1 = lrow1 * al1 + sum1;

        // rescale O
#pragma unroll
        for (int cf = 0; cf < 16; cf++) {
            o[cf][0] *= al0; o[cf][1] *= al0;
            o[cf][2] *= al1; o[cf][3] *= al1;
        }

        // ---- PV (fp16 m16n8k16): S C-frags map directly onto A-frags ----
#pragma unroll
        for (int kc = 0; kc < 4; kc++) {
            uint32_t a0 = f2h2(sf[2*kc][0],   sf[2*kc][1]);
            uint32_t a1 = f2h2(sf[2*kc][2],   sf[2*kc][3]);
            uint32_t a2 = f2h2(sf[2*kc+1][0], sf[2*kc+1][1]);
            uint32_t a3 = f2h2(sf[2*kc+1][2], sf[2*kc+1][3]);
#pragma unroll
            for (int cf = 0; cf < 16; cf++) {
                int c = cb + cf * 8 + r;
                uint32_t b0 = vs32[c * 36 + kc * 8 + q];
                uint32_t b1 = vs32[c * 36 + kc * 8 + q + 4];
                mma_f16(o[cf], a0, a1, a2, a3, b0, b1);
            }
        }

        __syncthreads();   // all warps done reading buffer bi
        if (t + 2 < NTILES) {
            stage_k(sb, b, (t + 2) * BN, bi, tid);
            stage_v(sb, b, (t + 2) * BN, bi, tid);
        }
        CP_COMMIT();       // always commit (possibly empty group) to keep count
    }

    // ---- epilogue: normalize + gamma, stage to smem, coalesced out ----
    const float g0 = __ldg(gamma);
    const float sc0 = g0 / lrow0;
    const float sc1 = g0 / lrow1;
    float* cs = (float*)(smem + OFF_V);   // [m][257]
#pragma unroll
    for (int cf = 0; cf < 16; cf++) {
        int c = cb + cf * 8 + 2 * q;
        cs[(m0 + r)     * 257 + c]     = o[cf][0] * sc0;
        cs[(m0 + r)     * 257 + c + 1] = o[cf][1] * sc0;
        cs[(m0 + r + 8) * 257 + c]     = o[cf][2] * sc1;
        cs[(m0 + r + 8) * 257 + c + 1] = o[cf][3] * sc1;
    }
    __syncthreads();

    const float4* x4 = (const float4*)x;
    float4* o4       = (float4*)out;
#pragma unroll
    for (int r2 = 0; r2 < 16; r2++) {
        int idx = tid + r2 * 256;
        int c  = idx >> 4;
        int mq = (idx & 15) * 4;
        size_t gi = (((size_t)(b * CC + c)) * NN + n0 + mq) >> 2;
        float4 xv = x4[gi];
        float4 ov;
        ov.x = cs[(mq + 0) * 257 + c] + xv.x;
        ov.y = cs[(mq + 1) * 257 + c] + xv.y;
        ov.z = cs[(mq + 2) * 257 + c] + xv.z;
        ov.w = cs[(mq + 3) * 257 + c] + xv.w;
        o4[gi] = ov;
    }
}

// ---------------------------------------------------------------------------
extern "C" void kernel_launch(void* const* d_in, const int* in_sizes, int n_in,
                              void* d_out, int out_size)
{
    const float* x     = (const float*)d_in[0];
    const float* Wq    = (const float*)d_in[1];
    const float* bq    = (const float*)d_in[2];
    const float* Wk    = (const float*)d_in[3];
    const float* bk    = (const float*)d_in[4];
    const float* Wv    = (const float*)d_in[5];
    const float* bv    = (const float*)d_in[6];
    const float* gamma = (const float*)d_in[7];
    float* out = (float*)d_out;

    (void)in_sizes; (void)n_in; (void)out_size;

    cudaFuncSetAttribute(attn_kernel,
                         cudaFuncAttributeMaxDynamicSharedMemorySize, SMEM_TOTAL);

    proj_kernel<<<dim3(NN / 32, BATCH), 256>>>(x, Wq, bq, Wk, bk, Wv, bv);
    attn_kernel<<<dim3(NN / BM, BATCH), 256, SMEM_TOTAL>>>(x, gamma, out);
}